// round 17
// baseline (speedup 1.0000x reference)
#include <cuda_runtime.h>
#include <cuda_bf16.h>
#include <cstdint>

#define D 64
#define MAXN 50000
#define MAXE 1000000
#define MAXR 10

// ---------------------------------------------------------------------------
// Scratch (__device__ globals: allocation-free rule)
// ---------------------------------------------------------------------------
__device__ __align__(16) float          g_xr[(size_t)MAXR * MAXN * D];   // [R,N,D] fp32
__device__ __align__(16) __nv_bfloat16  g_Bhi[(MAXR + 1) * D * D];       // W^T hi
__device__ __align__(16) __nv_bfloat16  g_Blo[(MAXR + 1) * D * D];       // W^T lo
__device__ int   g_cnt[MAXN];
__device__ int   g_cur[MAXN];
__device__ int   g_offs[MAXN + 1];
__device__ int   g_bsum[128];
__device__ __align__(8) uint2 g_payload[MAXE];                           // (r*N+src, norm)

// ---------------------------------------------------------------------------
// Helpers
// ---------------------------------------------------------------------------
__device__ __forceinline__ uint32_t smem_u32(const void* p) {
    uint32_t a;
    asm("{ .reg .u64 t; cvta.to.shared.u64 t, %1; cvt.u32.u64 %0, t; }" : "=r"(a) : "l"(p));
    return a;
}
__device__ __forceinline__ void ldsm_x4(uint32_t& r0, uint32_t& r1, uint32_t& r2, uint32_t& r3,
                                        uint32_t addr) {
    asm volatile("ldmatrix.sync.aligned.m8n8.x4.shared.b16 {%0,%1,%2,%3}, [%4];"
                 : "=r"(r0), "=r"(r1), "=r"(r2), "=r"(r3) : "r"(addr));
}
__device__ __forceinline__ void mma_bf16(float c[4], uint32_t a0, uint32_t a1, uint32_t a2,
                                         uint32_t a3, uint32_t b0, uint32_t b1) {
    asm volatile(
        "mma.sync.aligned.m16n8k16.row.col.f32.bf16.bf16.f32 "
        "{%0,%1,%2,%3},{%4,%5,%6,%7},{%8,%9},{%0,%1,%2,%3};"
        : "+f"(c[0]), "+f"(c[1]), "+f"(c[2]), "+f"(c[3])
        : "r"(a0), "r"(a1), "r"(a2), "r"(a3), "r"(b0), "r"(b1));
}

// ---------------------------------------------------------------------------
// K0: basis combine + transpose + hi/lo bf16 split.
// ---------------------------------------------------------------------------
__global__ void k0_prepW(const float* __restrict__ weight,
                         const float* __restrict__ w_comp,
                         const float* __restrict__ self_w,
                         int R, int B) {
    int r = blockIdx.x;
    for (int idx = threadIdx.x; idx < D * D; idx += blockDim.x) {
        int kk = idx >> 6, j = idx & 63;
        float w;
        if (r < R) {
            w = 0.f;
            for (int b = 0; b < B; b++)
                w += w_comp[r * B + b] * weight[b * D * D + idx];
        } else {
            w = self_w[idx];
        }
        __nv_bfloat16 hi = __float2bfloat16(w);
        __nv_bfloat16 lo = __float2bfloat16(w - __bfloat162float(hi));
        g_Bhi[r * D * D + j * D + kk] = hi;
        g_Blo[r * D * D + j * D + kk] = lo;
    }
}

// ---------------------------------------------------------------------------
// K1: HMMA bf16 hi/lo 3-pass GEMM (unchanged from R16 — passed at 4.4e-6).
// ---------------------------------------------------------------------------
#define ROWB 144
#define SM_AHI 0
#define SM_ALO (128 * ROWB)
#define SM_BHI (2 * 128 * ROWB)
#define SM_BLO (2 * 128 * ROWB + 64 * ROWB)
#define SM_TOTAL (2 * 128 * ROWB + 2 * 64 * ROWB)

__global__ __launch_bounds__(256, 2)
void k1_mma(const float* __restrict__ feat, float* __restrict__ out, int N, int R) {
    extern __shared__ char smem[];
    const uint32_t sb = smem_u32(smem);
    const int t    = threadIdx.x;
    const int wid  = t >> 5, lid = t & 31;
    const int r    = blockIdx.y;
    const int base = blockIdx.x * 128;

    {
        const uint4* bh = (const uint4*)(g_Bhi + (size_t)r * D * D);
        const uint4* bl = (const uint4*)(g_Blo + (size_t)r * D * D);
        #pragma unroll
        for (int i = 0; i < 2; i++) {
            int lin = t + i * 256;
            int row = lin >> 3, q = lin & 7;
            uint32_t doff = (uint32_t)row * ROWB + (uint32_t)q * 16;
            *(uint4*)(smem + SM_BHI + doff) = bh[lin];
            *(uint4*)(smem + SM_BLO + doff) = bl[lin];
        }
    }

    #pragma unroll
    for (int i = 0; i < 8; i++) {
        int lin = t + i * 256;
        int row = lin >> 4, c4 = lin & 15;
        int n = base + row;
        float4 v = make_float4(0.f, 0.f, 0.f, 0.f);
        if (n < N) v = *(const float4*)(feat + (size_t)n * D + c4 * 4);
        __nv_bfloat162 h01 = __floats2bfloat162_rn(v.x, v.y);
        __nv_bfloat162 h23 = __floats2bfloat162_rn(v.z, v.w);
        float lx = v.x - __bfloat162float(__low2bfloat16(h01));
        float ly = v.y - __bfloat162float(__high2bfloat16(h01));
        float lz = v.z - __bfloat162float(__low2bfloat16(h23));
        float lw = v.w - __bfloat162float(__high2bfloat16(h23));
        __nv_bfloat162 l01 = __floats2bfloat162_rn(lx, ly);
        __nv_bfloat162 l23 = __floats2bfloat162_rn(lz, lw);
        uint32_t doff = (uint32_t)row * ROWB + (uint32_t)c4 * 8;
        *(uint2*)(smem + SM_AHI + doff) = make_uint2(*(uint32_t*)&h01, *(uint32_t*)&h23);
        *(uint2*)(smem + SM_ALO + doff) = make_uint2(*(uint32_t*)&l01, *(uint32_t*)&l23);
    }
    __syncthreads();

    const int m0 = wid * 16;
    float acc[8][4];
    #pragma unroll
    for (int i = 0; i < 8; i++)
        #pragma unroll
        for (int j = 0; j < 4; j++) acc[i][j] = 0.f;

    const uint32_t a_lane = sb + (uint32_t)(m0 + (lid & 15)) * ROWB + ((lid >> 4) * 16);
    const uint32_t b_row  = (uint32_t)((lid & 7) + ((lid >> 4) & 1) * 8);
    const uint32_t b_lane = sb + SM_BHI + b_row * ROWB + (((lid >> 3) & 1) * 16);

    #pragma unroll
    for (int kc = 0; kc < 4; kc++) {
        uint32_t ah0, ah1, ah2, ah3, al0, al1, al2, al3;
        ldsm_x4(ah0, ah1, ah2, ah3, a_lane + SM_AHI + kc * 32);
        ldsm_x4(al0, al1, al2, al3, a_lane + SM_ALO + kc * 32);
        #pragma unroll
        for (int p = 0; p < 4; p++) {
            uint32_t bh0, bh1, bh2, bh3, bl0, bl1, bl2, bl3;
            uint32_t ba = b_lane + (uint32_t)p * 16 * ROWB + kc * 32;
            ldsm_x4(bh0, bh1, bh2, bh3, ba);
            ldsm_x4(bl0, bl1, bl2, bl3, ba + (SM_BLO - SM_BHI));
            mma_bf16(acc[2 * p],     ah0, ah1, ah2, ah3, bh0, bh1);
            mma_bf16(acc[2 * p],     ah0, ah1, ah2, ah3, bl0, bl1);
            mma_bf16(acc[2 * p],     al0, al1, al2, al3, bh0, bh1);
            mma_bf16(acc[2 * p + 1], ah0, ah1, ah2, ah3, bh2, bh3);
            mma_bf16(acc[2 * p + 1], ah0, ah1, ah2, ah3, bl2, bl3);
            mma_bf16(acc[2 * p + 1], al0, al1, al2, al3, bh2, bh3);
        }
    }

    float* dstbase = (r < R) ? (g_xr + (size_t)r * N * D) : out;
    int row0 = base + m0 + (lid >> 2);
    int col  = (lid & 3) * 2;
    #pragma unroll
    for (int nt = 0; nt < 8; nt++) {
        if (row0 < N)
            *(float2*)(dstbase + (size_t)row0 * D + nt * 8 + col) =
                make_float2(acc[nt][0], acc[nt][1]);
        if (row0 + 8 < N)
            *(float2*)(dstbase + (size_t)(row0 + 8) * D + nt * 8 + col) =
                make_float2(acc[nt][2], acc[nt][3]);
    }
}

// ---------------------------------------------------------------------------
// K2 chain: counting-sort edges by dst, then warp-per-node gather-aggregate.
// ---------------------------------------------------------------------------
__global__ void k2_zero(int N) {
    int i = blockIdx.x * 256 + threadIdx.x;
    if (i < N) { g_cnt[i] = 0; g_cur[i] = 0; }
}

__global__ void k2_hist(const int* __restrict__ dst, int E) {
    int e = blockIdx.x * 256 + threadIdx.x;
    if (e < E) atomicAdd(&g_cnt[dst[e]], 1);
}

#define SCAN_T 1024
__global__ void k2_scan1(int N) {   // per-block exclusive scan + block sums
    __shared__ int sh[SCAN_T];
    int i = blockIdx.x * SCAN_T + threadIdx.x;
    int x = (i < N) ? g_cnt[i] : 0;
    sh[threadIdx.x] = x;
    __syncthreads();
    #pragma unroll
    for (int off = 1; off < SCAN_T; off <<= 1) {
        int v = (threadIdx.x >= off) ? sh[threadIdx.x - off] : 0;
        __syncthreads();
        sh[threadIdx.x] += v;
        __syncthreads();
    }
    if (i < N) g_offs[i] = sh[threadIdx.x] - x;   // exclusive, block-local
    if (threadIdx.x == SCAN_T - 1) g_bsum[blockIdx.x] = sh[SCAN_T - 1];
}

__global__ void k2_scan2(int nb, int N, int E) {  // scan block sums (tiny)
    if (threadIdx.x == 0) {
        int run = 0;
        for (int b = 0; b < nb; b++) { int v = g_bsum[b]; g_bsum[b] = run; run += v; }
        g_offs[N] = E;
    }
}

__global__ void k2_scan3(int N) {
    int i = blockIdx.x * SCAN_T + threadIdx.x;
    if (i < N) g_offs[i] += g_bsum[blockIdx.x];
}

__global__ void k2_reorder(const int* __restrict__ src, const int* __restrict__ dst,
                           const int* __restrict__ etype, const float* __restrict__ norm,
                           int E, int N) {
    int e = blockIdx.x * 256 + threadIdx.x;
    if (e >= E) return;
    int d = dst[e];
    int pos = g_offs[d] + atomicAdd(&g_cur[d], 1);
    g_payload[pos] = make_uint2((uint32_t)(etype[e] * N + src[e]), __float_as_uint(norm[e]));
}

// Warp per dst node: gather g_xr rows, accumulate, add self-loop (already in
// out), ReLU, write back. Replaces both the atomic scatter and K3.
__global__ __launch_bounds__(256) void k2_agg(float* __restrict__ out, int N) {
    int warp = (blockIdx.x * 256 + threadIdx.x) >> 5;
    int lid  = threadIdx.x & 31;
    if (warp >= N) return;
    int s0 = g_offs[warp], s1 = g_offs[warp + 1];

    float2 acc = make_float2(0.f, 0.f);
    int e = s0;
    for (; e + 2 <= s1; e += 2) {
        uint2 p0 = __ldg(&g_payload[e]);
        uint2 p1 = __ldg(&g_payload[e + 1]);
        float2 v0 = *(const float2*)(g_xr + (size_t)p0.x * D + lid * 2);
        float2 v1 = *(const float2*)(g_xr + (size_t)p1.x * D + lid * 2);
        float n0 = __uint_as_float(p0.y), n1 = __uint_as_float(p1.y);
        acc.x += n0 * v0.x + n1 * v1.x;
        acc.y += n0 * v0.y + n1 * v1.y;
    }
    if (e < s1) {
        uint2 p0 = __ldg(&g_payload[e]);
        float2 v0 = *(const float2*)(g_xr + (size_t)p0.x * D + lid * 2);
        float n0 = __uint_as_float(p0.y);
        acc.x += n0 * v0.x;
        acc.y += n0 * v0.y;
    }

    float2* orow = (float2*)(out + (size_t)warp * D);
    float2 cur = orow[lid];
    cur.x = fmaxf(cur.x + acc.x, 0.f);
    cur.y = fmaxf(cur.y + acc.y, 0.f);
    orow[lid] = cur;
}

// ---------------------------------------------------------------------------
// Inputs: feat, src, dst, etype, norm, weight, w_comp, self_loop_weight
// ---------------------------------------------------------------------------
extern "C" void kernel_launch(void* const* d_in, const int* in_sizes, int n_in,
                              void* d_out, int out_size) {
    const float* feat   = (const float*)d_in[0];
    const int*   src    = (const int*)  d_in[1];
    const int*   dst    = (const int*)  d_in[2];
    const int*   etype  = (const int*)  d_in[3];
    const float* norm   = (const float*)d_in[4];
    const float* weight = (const float*)d_in[5];
    const float* w_comp = (const float*)d_in[6];
    const float* self_w = (const float*)d_in[7];
    float*       out    = (float*)d_out;

    const int N = in_sizes[0] / D;
    const int E = in_sizes[1];
    const int B = in_sizes[5] / (D * D);
    const int R = in_sizes[6] / B;

    cudaFuncSetAttribute(k1_mma, cudaFuncAttributeMaxDynamicSharedMemorySize, SM_TOTAL);

    // K0: basis combine
    k0_prepW<<<R + 1, 256>>>(weight, w_comp, self_w, R, B);

    // K1: 11 HMMA GEMMs (r == R writes self-loop into d_out)
    dim3 g1((N + 127) / 128, R + 1);
    k1_mma<<<g1, 256, SM_TOTAL>>>(feat, out, N, R);

    // K2: counting sort by dst
    int nb = (N + SCAN_T - 1) / SCAN_T;
    k2_zero<<<(N + 255) / 256, 256>>>(N);
    k2_hist<<<(E + 255) / 256, 256>>>(dst, E);
    k2_scan1<<<nb, SCAN_T>>>(N);
    k2_scan2<<<1, 32>>>(nb, N, E);
    k2_scan3<<<nb, SCAN_T>>>(N);
    k2_reorder<<<(E + 255) / 256, 256>>>(src, dst, etype, norm, E, N);

    // Aggregate + self-loop + ReLU (fused)
    int warps = N;
    k2_agg<<<(warps * 32 + 255) / 256, 256>>>(out, N);
}